// round 1
// baseline (speedup 1.0000x reference)
#include <cuda_runtime.h>
#include <cuda_bf16.h>
#include <math.h>

// Problem dims
#define TGT   64
#define SRC   64
#define BATCH 32
#define HID   512
#define ATT   512

// Scratch (no cudaMalloc allowed)
__device__ float g_hpart[TGT * BATCH * ATT];   // [t*BATCH+b][a]
__device__ float g_spart[SRC * BATCH * ATT];   // [s*BATCH+b][a]
__device__ float g_scores[TGT * BATCH * SRC];  // [(t*BATCH+b)*SRC + s]

// ---------------------------------------------------------------------------
// Kernel 1: fused pair of GEMMs.
//   z=0: g_hpart[m][a] = sum_h h_t[m][h] * Wa[h][a]        (m = t*BATCH+b)
//   z=1: g_spart[m][a] = sum_h src[m][h] * Wa[HID+h][a]
// Block tile 128(M) x 64(N), K-tile 8, 256 threads, 8x4 per thread.
// ---------------------------------------------------------------------------
__global__ __launch_bounds__(256) void gemm_both(
    const float* __restrict__ h_t,
    const float* __restrict__ src,
    const float* __restrict__ Wa)
{
    __shared__ float As[8][132];   // [k][m], pad 132 to dodge STS conflicts
    __shared__ float Bs[8][64];    // [k][n]

    const int z  = blockIdx.z;
    const float* A = (z == 0) ? h_t : src;
    const float* B = Wa + (z == 0 ? 0 : HID * ATT);
    float*       C = (z == 0) ? g_hpart : g_spart;

    const int m0 = blockIdx.y * 128;
    const int n0 = blockIdx.x * 64;
    const int tid = threadIdx.x;
    const int ty = tid >> 4;       // 0..15 -> m sub-tile of 8
    const int tx = tid & 15;       // 0..15 -> n sub-tile of 4

    // load indices
    const int lm = tid >> 1;            // 0..127
    const int lk = (tid & 1) * 4;       // 0 or 4
    const int bk = tid >> 5;            // 0..7
    const int bn = (tid & 31) * 2;      // 0..62

    float acc[8][4];
#pragma unroll
    for (int i = 0; i < 8; i++)
#pragma unroll
        for (int j = 0; j < 4; j++) acc[i][j] = 0.f;

    for (int k0 = 0; k0 < HID; k0 += 8) {
        float4 av = *(const float4*)(A + (m0 + lm) * HID + k0 + lk);
        As[lk + 0][lm] = av.x;
        As[lk + 1][lm] = av.y;
        As[lk + 2][lm] = av.z;
        As[lk + 3][lm] = av.w;
        float2 bv = *(const float2*)(B + (k0 + bk) * ATT + n0 + bn);
        Bs[bk][bn]     = bv.x;
        Bs[bk][bn + 1] = bv.y;
        __syncthreads();

#pragma unroll
        for (int kk = 0; kk < 8; kk++) {
            float4 a0 = *(const float4*)&As[kk][ty * 8];
            float4 a1 = *(const float4*)&As[kk][ty * 8 + 4];
            float4 b0 = *(const float4*)&Bs[kk][tx * 4];
            float ar[8] = {a0.x, a0.y, a0.z, a0.w, a1.x, a1.y, a1.z, a1.w};
            float br[4] = {b0.x, b0.y, b0.z, b0.w};
#pragma unroll
            for (int i = 0; i < 8; i++)
#pragma unroll
                for (int j = 0; j < 4; j++) acc[i][j] = fmaf(ar[i], br[j], acc[i][j]);
        }
        __syncthreads();
    }

#pragma unroll
    for (int i = 0; i < 8; i++) {
        float4 v = make_float4(acc[i][0], acc[i][1], acc[i][2], acc[i][3]);
        *(float4*)(C + (m0 + ty * 8 + i) * ATT + n0 + tx * 4) = v;
    }
}

// ---------------------------------------------------------------------------
// Kernel 2: scores[s,t,b] = sum_a tanh(h_part[t,b,a] + s_part[s,b,a]) * Va[a]
// Block: one b, 16 t's, 32 s's (grid.x picks s-half). 256 threads,
// each thread owns one (s,t) pair per 16-s chunk. Operands staged in smem.
// ---------------------------------------------------------------------------
#define SSTR 516   // smem row stride (floats), 516*4 % 16 == 0, low conflicts

__global__ __launch_bounds__(256) void scores_kernel(
    const float* __restrict__ Va)
{
    extern __shared__ float sm[];
    float* hs = sm;                 // 16 * SSTR
    float* ss = sm + 16 * SSTR;     // 16 * SSTR
    float* va = sm + 32 * SSTR;     // 512

    const int b     = blockIdx.z;
    const int t0    = blockIdx.y * 16;
    const int sbase = blockIdx.x * 32;
    const int tid   = threadIdx.x;

    va[tid]       = Va[tid];
    va[tid + 256] = Va[tid + 256];

    // stage 16 h_part rows
#pragma unroll
    for (int r = 0; r < 8; r++) {
        int idx  = r * 256 + tid;      // 0..2047 float4 slots
        int row  = idx >> 7;           // /128
        int col4 = idx & 127;
        float4 v = *(const float4*)(g_hpart + ((t0 + row) * BATCH + b) * ATT + col4 * 4);
        *(float4*)(hs + row * SSTR + col4 * 4) = v;
    }

    const int si = tid & 15;
    const int ti = tid >> 4;

    for (int sc = 0; sc < 32; sc += 16) {
        __syncthreads();   // previous chunk's compute done (no-op cost 1st iter)
        // stage 16 s_part rows
#pragma unroll
        for (int r = 0; r < 8; r++) {
            int idx  = r * 256 + tid;
            int row  = idx >> 7;
            int col4 = idx & 127;
            float4 v = *(const float4*)(g_spart + ((sbase + sc + row) * BATCH + b) * ATT + col4 * 4);
            *(float4*)(ss + row * SSTR + col4 * 4) = v;
        }
        __syncthreads();

        const float* hp = hs + ti * SSTR;
        const float* sp = ss + si * SSTR;
        float acc = 0.f;
#pragma unroll 4
        for (int a = 0; a < 512; a += 4) {
            float4 h4 = *(const float4*)(hp + a);
            float4 s4 = *(const float4*)(sp + a);
            float4 v4 = *(const float4*)(va + a);
            acc = fmaf(tanhf(h4.x + s4.x), v4.x, acc);
            acc = fmaf(tanhf(h4.y + s4.y), v4.y, acc);
            acc = fmaf(tanhf(h4.z + s4.z), v4.z, acc);
            acc = fmaf(tanhf(h4.w + s4.w), v4.w, acc);
        }
        const int s = sbase + sc + si;
        const int t = t0 + ti;
        g_scores[(t * BATCH + b) * SRC + s] = acc;
    }
}

// ---------------------------------------------------------------------------
// Kernel 3: softmax over s, then context[t,b,h] = sum_s attn[s,t,b]*src[s,b,h]
// Block: one b, group of 8 t's. 256 threads. Each warp softmaxes one t;
// then each thread accumulates 8 t-rows for 2 h positions (8 FMA per load).
// ---------------------------------------------------------------------------
__global__ __launch_bounds__(256) void softmax_context_kernel(
    const float* __restrict__ src,
    float* __restrict__ out)
{
    __shared__ float w[8][64];

    const int b   = blockIdx.y;
    const int t0  = blockIdx.x * 8;
    const int tid = threadIdx.x;
    const int wi   = tid >> 5;
    const int lane = tid & 31;

    // softmax for t = t0 + wi (one warp each)
    const float* srow = g_scores + ((t0 + wi) * BATCH + b) * SRC;
    float v0 = srow[lane];
    float v1 = srow[lane + 32];
    float mx = fmaxf(v0, v1);
#pragma unroll
    for (int o = 16; o > 0; o >>= 1)
        mx = fmaxf(mx, __shfl_xor_sync(0xffffffffu, mx, o));
    float e0 = __expf(v0 - mx);
    float e1 = __expf(v1 - mx);
    float sum = e0 + e1;
#pragma unroll
    for (int o = 16; o > 0; o >>= 1)
        sum += __shfl_xor_sync(0xffffffffu, sum, o);
    float inv = 1.0f / sum;
    w[wi][lane]      = e0 * inv;
    w[wi][lane + 32] = e1 * inv;
    __syncthreads();

    // context accumulation: h0 = tid, h1 = tid + 256
    float acc0[8], acc1[8];
#pragma unroll
    for (int i = 0; i < 8; i++) { acc0[i] = 0.f; acc1[i] = 0.f; }

    const int h0 = tid;
    const int h1 = tid + 256;
#pragma unroll 4
    for (int s = 0; s < SRC; s++) {
        float x0 = src[(s * BATCH + b) * HID + h0];
        float x1 = src[(s * BATCH + b) * HID + h1];
#pragma unroll
        for (int i = 0; i < 8; i++) {
            float ws = w[i][s];
            acc0[i] = fmaf(ws, x0, acc0[i]);
            acc1[i] = fmaf(ws, x1, acc1[i]);
        }
    }

#pragma unroll
    for (int i = 0; i < 8; i++) {
        out[((t0 + i) * BATCH + b) * HID + h0] = acc0[i];
        out[((t0 + i) * BATCH + b) * HID + h1] = acc1[i];
    }
}

// ---------------------------------------------------------------------------
extern "C" void kernel_launch(void* const* d_in, const int* in_sizes, int n_in,
                              void* d_out, int out_size)
{
    const float* h_t  = (const float*)d_in[0];   // (64, 32, 512)
    const float* srce = (const float*)d_in[1];   // (64, 32, 512)
    const float* Wa   = (const float*)d_in[2];   // (1024, 512)
    const float* Va   = (const float*)d_in[3];   // (512,)
    float* out = (float*)d_out;                  // (64, 32, 512)

    (void)in_sizes; (void)n_in; (void)out_size;

    // GEMMs: grid (N/64=8, M/128=16, 2)
    gemm_both<<<dim3(8, 16, 2), 256>>>(h_t, srce, Wa);

    // Scores: grid (s-halves=2, t-tiles=4, b=32), 256 threads, ~68KB dyn smem
    const int smem_bytes = (32 * SSTR + 512) * sizeof(float);
    cudaFuncSetAttribute(scores_kernel,
                         cudaFuncAttributeMaxDynamicSharedMemorySize, smem_bytes);
    scores_kernel<<<dim3(2, 4, 32), 256, smem_bytes>>>(Va);

    // Softmax + context: grid (t-groups=8, b=32)
    softmax_context_kernel<<<dim3(8, 32), 256>>>(srce, out);
}

// round 3
// speedup vs baseline: 1.3813x; 1.3813x over previous
#include <cuda_runtime.h>
#include <cuda_bf16.h>
#include <math.h>
#include <cstdint>

// Problem dims
#define TGT   64
#define SRC   64
#define BATCH 32
#define HID   512
#define ATT   512

// Scratch (no cudaMalloc allowed)
__device__ float g_hpart[TGT * BATCH * ATT];   // [t*BATCH+b][a]
__device__ float g_spart[SRC * BATCH * ATT];   // [s*BATCH+b][a]
__device__ float g_scores[TGT * BATCH * SRC];  // [(t*BATCH+b)*SRC + s]
__device__ float g_WT[2 * HID * ATT];          // W transposed: [z][n][k]

// ---------------------------------------------------------------------------
// helpers
// ---------------------------------------------------------------------------
__device__ __forceinline__ float to_tf32(float x) {
    uint32_t u;
    asm("cvt.rna.tf32.f32 %0, %1;" : "=r"(u) : "f"(x));
    return __uint_as_float(u);
}

__device__ __forceinline__ void mma_tf32(float* c, const float* a, const float* b) {
    uint32_t a0 = __float_as_uint(a[0]), a1 = __float_as_uint(a[1]);
    uint32_t a2 = __float_as_uint(a[2]), a3 = __float_as_uint(a[3]);
    uint32_t b0 = __float_as_uint(b[0]), b1 = __float_as_uint(b[1]);
    asm volatile(
        "mma.sync.aligned.m16n8k8.row.col.f32.tf32.tf32.f32 "
        "{%0,%1,%2,%3}, {%4,%5,%6,%7}, {%8,%9}, {%0,%1,%2,%3};"
        : "+f"(c[0]), "+f"(c[1]), "+f"(c[2]), "+f"(c[3])
        : "r"(a0), "r"(a1), "r"(a2), "r"(a3), "r"(b0), "r"(b1));
}

// ---------------------------------------------------------------------------
// Kernel 0: transpose W halves: g_WT[z][n][k] = Wa[z*512 + k][n]
// ---------------------------------------------------------------------------
__global__ __launch_bounds__(256) void transpose_w(const float* __restrict__ Wa)
{
    __shared__ float t[32][33];
    const int tx = threadIdx.x, ty = threadIdx.y;
    const int k0 = blockIdx.x * 32, n0 = blockIdx.y * 32, z = blockIdx.z;
#pragma unroll
    for (int r = 0; r < 32; r += 8)
        t[ty + r][tx] = Wa[(z * HID + k0 + ty + r) * ATT + n0 + tx];
    __syncthreads();
#pragma unroll
    for (int r = 0; r < 32; r += 8)
        g_WT[z * HID * ATT + (n0 + ty + r) * HID + k0 + tx] = t[tx][ty + r];
}

// ---------------------------------------------------------------------------
// Kernel 1: tf32 mma.sync GEMM.  C[m][n] = sum_k A[m][k] * WT[n][k]
//   z = mtile>>4:  z=0 -> A=h_t, C=g_hpart;  z=1 -> A=src, C=g_spart
// CTA tile 128(M) x 128(N), K in 16 double-buffered stages of 32.
// 8 warps: warp tile 32(M) x 64(N) -> 2 x 8 m16n8k8 frags.
// Smem rows stride 36 floats -> conflict-free fragment LDS and STS.128.
// ---------------------------------------------------------------------------
#define KT    32
#define RSTR  36                       // floats per smem row
#define TILEF (128 * RSTR)             // floats per operand tile (4608)

__global__ __launch_bounds__(256) void gemm_mma(
    const float* __restrict__ h_t,
    const float* __restrict__ src)
{
    extern __shared__ __align__(16) float sm[];
    // [A0 | B0 | A1 | B1]
    float* const Abuf[2] = { sm,             sm + 2 * TILEF };
    float* const Bbuf[2] = { sm + TILEF,     sm + 3 * TILEF };

    const int tid  = threadIdx.x;
    const int lane = tid & 31;
    const int wid  = tid >> 5;
    const int g    = lane >> 2;      // group id (row within frag)
    const int tg   = lane & 3;       // thread in group (col within frag)

    const int wm = (wid >> 1) * 32;  // warp M offset: 0,32,64,96
    const int wn = (wid & 1) * 64;   // warp N offset: 0,64

    const int ntile = blockIdx.x;    // 0..3
    const int mtile = blockIdx.y;    // 0..31
    const int z  = mtile >> 4;
    const float* A = (z == 0) ? h_t : src;
    const float* B = g_WT + z * HID * ATT;
    float*       C = (z == 0) ? g_hpart : g_spart;
    const int m0 = (mtile & 15) * 128;
    const int n0 = ntile * 128;

    // staging index: 4 float4 per operand per thread
    const int srow = tid >> 1;              // unused placeholder (see loop)
    (void)srow;

    float acc[2][8][4];
#pragma unroll
    for (int mi = 0; mi < 2; mi++)
#pragma unroll
        for (int ni = 0; ni < 8; ni++)
#pragma unroll
            for (int j = 0; j < 4; j++) acc[mi][ni][j] = 0.f;

    // ---- stage 0 ----
#pragma unroll
    for (int r = 0; r < 4; r++) {
        const int idx = r * 256 + tid;
        const int row = idx >> 3;
        const int c4  = idx & 7;
        float4 av = *(const float4*)(A + (m0 + row) * HID + c4 * 4);
        float4 bv = *(const float4*)(B + (n0 + row) * HID + c4 * 4);
        float* da = Abuf[0] + row * RSTR + c4 * 4;
        float* db = Bbuf[0] + row * RSTR + c4 * 4;
        *(float4*)da = make_float4(to_tf32(av.x), to_tf32(av.y), to_tf32(av.z), to_tf32(av.w));
        *(float4*)db = make_float4(to_tf32(bv.x), to_tf32(bv.y), to_tf32(bv.z), to_tf32(bv.w));
    }
    __syncthreads();

    for (int s = 0; s < 16; s++) {
        const int cur = s & 1;
        float4 ra[4], rb[4];
        if (s < 15) {
            const int kt = (s + 1) * KT;
#pragma unroll
            for (int r = 0; r < 4; r++) {
                const int idx = r * 256 + tid;
                const int row = idx >> 3;
                const int c4  = idx & 7;
                ra[r] = *(const float4*)(A + (m0 + row) * HID + kt + c4 * 4);
                rb[r] = *(const float4*)(B + (n0 + row) * HID + kt + c4 * 4);
            }
        }

        // ---- compute current buffer: 4 k-steps of 8 ----
        const float* Ab = Abuf[cur];
        const float* Bb = Bbuf[cur];
#pragma unroll
        for (int ks = 0; ks < 4; ks++) {
            const int k0 = ks * 8;
            float a[2][4];
#pragma unroll
            for (int mi = 0; mi < 2; mi++) {
                const float* ap = Ab + (wm + mi * 16 + g) * RSTR + k0 + tg;
                a[mi][0] = ap[0];
                a[mi][1] = ap[8 * RSTR];
                a[mi][2] = ap[4];
                a[mi][3] = ap[8 * RSTR + 4];
            }
            float b[8][2];
#pragma unroll
            for (int ni = 0; ni < 8; ni++) {
                const float* bp = Bb + (wn + ni * 8 + g) * RSTR + k0 + tg;
                b[ni][0] = bp[0];
                b[ni][1] = bp[4];
            }
#pragma unroll
            for (int mi = 0; mi < 2; mi++)
#pragma unroll
                for (int ni = 0; ni < 8; ni++)
                    mma_tf32(acc[mi][ni], a[mi], b[ni]);
        }

        if (s < 15) {
            __syncthreads();   // everyone done reading buf[cur^1] two stages ago? (see note)
            const int nxt = cur ^ 1;
#pragma unroll
            for (int r = 0; r < 4; r++) {
                const int idx = r * 256 + tid;
                const int row = idx >> 3;
                const int c4  = idx & 7;
                float* da = Abuf[nxt] + row * RSTR + c4 * 4;
                float* db = Bbuf[nxt] + row * RSTR + c4 * 4;
                *(float4*)da = make_float4(to_tf32(ra[r].x), to_tf32(ra[r].y),
                                           to_tf32(ra[r].z), to_tf32(ra[r].w));
                *(float4*)db = make_float4(to_tf32(rb[r].x), to_tf32(rb[r].y),
                                           to_tf32(rb[r].z), to_tf32(rb[r].w));
            }
            __syncthreads();
        }
    }

    // ---- writeback ----
#pragma unroll
    for (int mi = 0; mi < 2; mi++) {
#pragma unroll
        for (int ni = 0; ni < 8; ni++) {
            const int row = m0 + wm + mi * 16 + g;
            const int col = n0 + wn + ni * 8 + 2 * tg;
            *(float2*)(C + row * ATT + col)       = make_float2(acc[mi][ni][0], acc[mi][ni][1]);
            *(float2*)(C + (row + 8) * ATT + col) = make_float2(acc[mi][ni][2], acc[mi][ni][3]);
        }
    }
}

// ---------------------------------------------------------------------------
// Kernel 2: scores[s,t,b] = sum_a tanh(h_part[t,b,a] + s_part[s,b,a]) * Va[a]
// ---------------------------------------------------------------------------
#define SSTR 516

__global__ __launch_bounds__(256) void scores_kernel(
    const float* __restrict__ Va)
{
    extern __shared__ float smem[];
    float* hs = smem;                 // 16 * SSTR
    float* ss = smem + 16 * SSTR;     // 16 * SSTR
    float* va = smem + 32 * SSTR;     // 512

    const int b     = blockIdx.z;
    const int t0    = blockIdx.y * 16;
    const int sbase = blockIdx.x * 32;
    const int tid   = threadIdx.x;

    va[tid]       = Va[tid];
    va[tid + 256] = Va[tid + 256];

#pragma unroll
    for (int r = 0; r < 8; r++) {
        int idx  = r * 256 + tid;
        int row  = idx >> 7;
        int col4 = idx & 127;
        float4 v = *(const float4*)(g_hpart + ((t0 + row) * BATCH + b) * ATT + col4 * 4);
        *(float4*)(hs + row * SSTR + col4 * 4) = v;
    }

    const int si = tid & 15;
    const int ti = tid >> 4;

    for (int sc = 0; sc < 32; sc += 16) {
        __syncthreads();
#pragma unroll
        for (int r = 0; r < 8; r++) {
            int idx  = r * 256 + tid;
            int row  = idx >> 7;
            int col4 = idx & 127;
            float4 v = *(const float4*)(g_spart + ((sbase + sc + row) * BATCH + b) * ATT + col4 * 4);
            *(float4*)(ss + row * SSTR + col4 * 4) = v;
        }
        __syncthreads();

        const float* hp = hs + ti * SSTR;
        const float* sp = ss + si * SSTR;
        float acc = 0.f;
#pragma unroll 4
        for (int a = 0; a < 512; a += 4) {
            float4 h4 = *(const float4*)(hp + a);
            float4 s4 = *(const float4*)(sp + a);
            float4 v4 = *(const float4*)(va + a);
            acc = fmaf(tanhf(h4.x + s4.x), v4.x, acc);
            acc = fmaf(tanhf(h4.y + s4.y), v4.y, acc);
            acc = fmaf(tanhf(h4.z + s4.z), v4.z, acc);
            acc = fmaf(tanhf(h4.w + s4.w), v4.w, acc);
        }
        const int s = sbase + sc + si;
        const int t = t0 + ti;
        g_scores[(t * BATCH + b) * SRC + s] = acc;
    }
}

// ---------------------------------------------------------------------------
// Kernel 3: softmax over s, context[t,b,h] = sum_s attn[s,t,b]*src[s,b,h]
// ---------------------------------------------------------------------------
__global__ __launch_bounds__(256) void softmax_context_kernel(
    const float* __restrict__ src,
    float* __restrict__ out)
{
    __shared__ float w[8][64];

    const int b   = blockIdx.y;
    const int t0  = blockIdx.x * 8;
    const int tid = threadIdx.x;
    const int wi   = tid >> 5;
    const int lane = tid & 31;

    const float* srow = g_scores + ((t0 + wi) * BATCH + b) * SRC;
    float v0 = srow[lane];
    float v1 = srow[lane + 32];
    float mx = fmaxf(v0, v1);
#pragma unroll
    for (int o = 16; o > 0; o >>= 1)
        mx = fmaxf(mx, __shfl_xor_sync(0xffffffffu, mx, o));
    float e0 = __expf(v0 - mx);
    float e1 = __expf(v1 - mx);
    float sum = e0 + e1;
#pragma unroll
    for (int o = 16; o > 0; o >>= 1)
        sum += __shfl_xor_sync(0xffffffffu, sum, o);
    float inv = 1.0f / sum;
    w[wi][lane]      = e0 * inv;
    w[wi][lane + 32] = e1 * inv;
    __syncthreads();

    float acc0[8], acc1[8];
#pragma unroll
    for (int i = 0; i < 8; i++) { acc0[i] = 0.f; acc1[i] = 0.f; }

    const int h0 = tid;
    const int h1 = tid + 256;
#pragma unroll 4
    for (int s = 0; s < SRC; s++) {
        float x0 = src[(s * BATCH + b) * HID + h0];
        float x1 = src[(s * BATCH + b) * HID + h1];
#pragma unroll
        for (int i = 0; i < 8; i++) {
            float ws = w[i][s];
            acc0[i] = fmaf(ws, x0, acc0[i]);
            acc1[i] = fmaf(ws, x1, acc1[i]);
        }
    }

#pragma unroll
    for (int i = 0; i < 8; i++) {
        out[((t0 + i) * BATCH + b) * HID + h0] = acc0[i];
        out[((t0 + i) * BATCH + b) * HID + h1] = acc1[i];
    }
}

// ---------------------------------------------------------------------------
extern "C" void kernel_launch(void* const* d_in, const int* in_sizes, int n_in,
                              void* d_out, int out_size)
{
    const float* h_t  = (const float*)d_in[0];   // (64, 32, 512)
    const float* srce = (const float*)d_in[1];   // (64, 32, 512)
    const float* Wa   = (const float*)d_in[2];   // (1024, 512)
    const float* Va   = (const float*)d_in[3];   // (512,)
    float* out = (float*)d_out;                  // (64, 32, 512)

    (void)in_sizes; (void)n_in; (void)out_size;

    // 0) transpose W halves into g_WT
    transpose_w<<<dim3(16, 16, 2), dim3(32, 8)>>>(Wa);

    // 1) tf32 mma GEMMs: grid (n tiles = 4, m tiles = 32) = 128 CTAs
    const int gemm_smem = 4 * TILEF * (int)sizeof(float);   // 73728 B
    cudaFuncSetAttribute(gemm_mma,
                         cudaFuncAttributeMaxDynamicSharedMemorySize, gemm_smem);
    gemm_mma<<<dim3(4, 32), 256, gemm_smem>>>(h_t, srce);

    // 2) scores: grid (s-halves=2, t-tiles=4, b=32)
    const int smem_bytes = (32 * SSTR + 512) * sizeof(float);
    cudaFuncSetAttribute(scores_kernel,
                         cudaFuncAttributeMaxDynamicSharedMemorySize, smem_bytes);
    scores_kernel<<<dim3(2, 4, 32), 256, smem_bytes>>>(Va);

    // 3) softmax + context
    softmax_context_kernel<<<dim3(8, 32), 256>>>(srce, out);
}

// round 4
// speedup vs baseline: 1.9648x; 1.4224x over previous
#include <cuda_runtime.h>
#include <cuda_bf16.h>
#include <math.h>
#include <cstdint>

// Problem dims
#define TGT   64
#define SRC   64
#define BATCH 32
#define HID   512
#define ATT   512

// Scratch (no cudaMalloc allowed)
__device__ float g_hpart[TGT * BATCH * ATT];   // [t*BATCH+b][a]
__device__ float g_spart[SRC * BATCH * ATT];   // [s*BATCH+b][a]
__device__ float g_scores[TGT * BATCH * SRC];  // [(t*BATCH+b)*SRC + s]
__device__ float g_WT[2 * HID * ATT];          // W transposed: [z][n][k]

// ---------------------------------------------------------------------------
// helpers
// ---------------------------------------------------------------------------
__device__ __forceinline__ float to_tf32(float x) {
    uint32_t u;
    asm("cvt.rna.tf32.f32 %0, %1;" : "=r"(u) : "f"(x));
    return __uint_as_float(u);
}

__device__ __forceinline__ float tanh_fast(float x) {
    float y;
    asm("tanh.approx.f32 %0, %1;" : "=f"(y) : "f"(x));
    return y;
}

__device__ __forceinline__ void mma_tf32(float* c, const float* a, const float* b) {
    uint32_t a0 = __float_as_uint(a[0]), a1 = __float_as_uint(a[1]);
    uint32_t a2 = __float_as_uint(a[2]), a3 = __float_as_uint(a[3]);
    uint32_t b0 = __float_as_uint(b[0]), b1 = __float_as_uint(b[1]);
    asm volatile(
        "mma.sync.aligned.m16n8k8.row.col.f32.tf32.tf32.f32 "
        "{%0,%1,%2,%3}, {%4,%5,%6,%7}, {%8,%9}, {%0,%1,%2,%3};"
        : "+f"(c[0]), "+f"(c[1]), "+f"(c[2]), "+f"(c[3])
        : "r"(a0), "r"(a1), "r"(a2), "r"(a3), "r"(b0), "r"(b1));
}

// ---------------------------------------------------------------------------
// Kernel 0: transpose W halves: g_WT[z][n][k] = Wa[z*512 + k][n]
// ---------------------------------------------------------------------------
__global__ __launch_bounds__(256) void transpose_w(const float* __restrict__ Wa)
{
    __shared__ float t[32][33];
    const int tx = threadIdx.x, ty = threadIdx.y;
    const int k0 = blockIdx.x * 32, n0 = blockIdx.y * 32, z = blockIdx.z;
#pragma unroll
    for (int r = 0; r < 32; r += 8)
        t[ty + r][tx] = Wa[(z * HID + k0 + ty + r) * ATT + n0 + tx];
    __syncthreads();
#pragma unroll
    for (int r = 0; r < 32; r += 8)
        g_WT[z * HID * ATT + (n0 + ty + r) * HID + k0 + tx] = t[tx][ty + r];
}

// ---------------------------------------------------------------------------
// Kernel 1: tf32 mma.sync GEMM.  C[m][n] = sum_k A[m][k] * WT[n][k]
// (unchanged from R3 — 128x128 CTA tile, KT=32 double-buffered, RNA staging)
// ---------------------------------------------------------------------------
#define KT    32
#define RSTR  36
#define TILEF (128 * RSTR)

__global__ __launch_bounds__(256) void gemm_mma(
    const float* __restrict__ h_t,
    const float* __restrict__ src)
{
    extern __shared__ __align__(16) float sm[];
    float* const Abuf[2] = { sm,         sm + 2 * TILEF };
    float* const Bbuf[2] = { sm + TILEF, sm + 3 * TILEF };

    const int tid  = threadIdx.x;
    const int lane = tid & 31;
    const int wid  = tid >> 5;
    const int g    = lane >> 2;
    const int tg   = lane & 3;

    const int wm = (wid >> 1) * 32;
    const int wn = (wid & 1) * 64;

    const int ntile = blockIdx.x;
    const int mtile = blockIdx.y;
    const int z  = mtile >> 4;
    const float* A = (z == 0) ? h_t : src;
    const float* B = g_WT + z * HID * ATT;
    float*       C = (z == 0) ? g_hpart : g_spart;
    const int m0 = (mtile & 15) * 128;
    const int n0 = ntile * 128;

    float acc[2][8][4];
#pragma unroll
    for (int mi = 0; mi < 2; mi++)
#pragma unroll
        for (int ni = 0; ni < 8; ni++)
#pragma unroll
            for (int j = 0; j < 4; j++) acc[mi][ni][j] = 0.f;

#pragma unroll
    for (int r = 0; r < 4; r++) {
        const int idx = r * 256 + tid;
        const int row = idx >> 3;
        const int c4  = idx & 7;
        float4 av = *(const float4*)(A + (m0 + row) * HID + c4 * 4);
        float4 bv = *(const float4*)(B + (n0 + row) * HID + c4 * 4);
        float* da = Abuf[0] + row * RSTR + c4 * 4;
        float* db = Bbuf[0] + row * RSTR + c4 * 4;
        *(float4*)da = make_float4(to_tf32(av.x), to_tf32(av.y), to_tf32(av.z), to_tf32(av.w));
        *(float4*)db = make_float4(to_tf32(bv.x), to_tf32(bv.y), to_tf32(bv.z), to_tf32(bv.w));
    }
    __syncthreads();

    for (int s = 0; s < 16; s++) {
        const int cur = s & 1;
        float4 ra[4], rb[4];
        if (s < 15) {
            const int kt = (s + 1) * KT;
#pragma unroll
            for (int r = 0; r < 4; r++) {
                const int idx = r * 256 + tid;
                const int row = idx >> 3;
                const int c4  = idx & 7;
                ra[r] = *(const float4*)(A + (m0 + row) * HID + kt + c4 * 4);
                rb[r] = *(const float4*)(B + (n0 + row) * HID + kt + c4 * 4);
            }
        }

        const float* Ab = Abuf[cur];
        const float* Bb = Bbuf[cur];
#pragma unroll
        for (int ks = 0; ks < 4; ks++) {
            const int k0 = ks * 8;
            float a[2][4];
#pragma unroll
            for (int mi = 0; mi < 2; mi++) {
                const float* ap = Ab + (wm + mi * 16 + g) * RSTR + k0 + tg;
                a[mi][0] = ap[0];
                a[mi][1] = ap[8 * RSTR];
                a[mi][2] = ap[4];
                a[mi][3] = ap[8 * RSTR + 4];
            }
            float b[8][2];
#pragma unroll
            for (int ni = 0; ni < 8; ni++) {
                const float* bp = Bb + (wn + ni * 8 + g) * RSTR + k0 + tg;
                b[ni][0] = bp[0];
                b[ni][1] = bp[4];
            }
#pragma unroll
            for (int mi = 0; mi < 2; mi++)
#pragma unroll
                for (int ni = 0; ni < 8; ni++)
                    mma_tf32(acc[mi][ni], a[mi], b[ni]);
        }

        if (s < 15) {
            __syncthreads();
            const int nxt = cur ^ 1;
#pragma unroll
            for (int r = 0; r < 4; r++) {
                const int idx = r * 256 + tid;
                const int row = idx >> 3;
                const int c4  = idx & 7;
                float* da = Abuf[nxt] + row * RSTR + c4 * 4;
                float* db = Bbuf[nxt] + row * RSTR + c4 * 4;
                *(float4*)da = make_float4(to_tf32(ra[r].x), to_tf32(ra[r].y),
                                           to_tf32(ra[r].z), to_tf32(ra[r].w));
                *(float4*)db = make_float4(to_tf32(rb[r].x), to_tf32(rb[r].y),
                                           to_tf32(rb[r].z), to_tf32(rb[r].w));
            }
            __syncthreads();
        }
    }

#pragma unroll
    for (int mi = 0; mi < 2; mi++) {
#pragma unroll
        for (int ni = 0; ni < 8; ni++) {
            const int row = m0 + wm + mi * 16 + g;
            const int col = n0 + wn + ni * 8 + 2 * tg;
            *(float2*)(C + row * ATT + col)       = make_float2(acc[mi][ni][0], acc[mi][ni][1]);
            *(float2*)(C + (row + 8) * ATT + col) = make_float2(acc[mi][ni][2], acc[mi][ni][3]);
        }
    }
}

// ---------------------------------------------------------------------------
// Kernel 2: scores[s,t,b] = sum_a tanh(h_part[t,b,a] + s_part[s,b,a]) * Va[a]
// tanh via MUFU.TANH (tanh.approx.f32) — MUFU-bound ~16us.
// ---------------------------------------------------------------------------
#define SSTR 516

__global__ __launch_bounds__(256) void scores_kernel(
    const float* __restrict__ Va)
{
    extern __shared__ float smem[];
    float* hs = smem;                 // 16 * SSTR
    float* ss = smem + 16 * SSTR;     // 16 * SSTR
    float* va = smem + 32 * SSTR;     // 512

    const int b     = blockIdx.z;
    const int t0    = blockIdx.y * 16;
    const int sbase = blockIdx.x * 32;
    const int tid   = threadIdx.x;

    va[tid]       = Va[tid];
    va[tid + 256] = Va[tid + 256];

#pragma unroll
    for (int r = 0; r < 8; r++) {
        int idx  = r * 256 + tid;
        int row  = idx >> 7;
        int col4 = idx & 127;
        float4 v = *(const float4*)(g_hpart + ((t0 + row) * BATCH + b) * ATT + col4 * 4);
        *(float4*)(hs + row * SSTR + col4 * 4) = v;
    }

    const int si = tid & 15;
    const int ti = tid >> 4;

    for (int sc = 0; sc < 32; sc += 16) {
        __syncthreads();
#pragma unroll
        for (int r = 0; r < 8; r++) {
            int idx  = r * 256 + tid;
            int row  = idx >> 7;
            int col4 = idx & 127;
            float4 v = *(const float4*)(g_spart + ((sbase + sc + row) * BATCH + b) * ATT + col4 * 4);
            *(float4*)(ss + row * SSTR + col4 * 4) = v;
        }
        __syncthreads();

        const float* hp = hs + ti * SSTR;
        const float* sp = ss + si * SSTR;
        float acc = 0.f;
#pragma unroll 4
        for (int a = 0; a < 512; a += 4) {
            float4 h4 = *(const float4*)(hp + a);
            float4 s4 = *(const float4*)(sp + a);
            float4 v4 = *(const float4*)(va + a);
            acc = fmaf(tanh_fast(h4.x + s4.x), v4.x, acc);
            acc = fmaf(tanh_fast(h4.y + s4.y), v4.y, acc);
            acc = fmaf(tanh_fast(h4.z + s4.z), v4.z, acc);
            acc = fmaf(tanh_fast(h4.w + s4.w), v4.w, acc);
        }
        const int s = sbase + sc + si;
        const int t = t0 + ti;
        g_scores[(t * BATCH + b) * SRC + s] = acc;
    }
}

// ---------------------------------------------------------------------------
// Kernel 3: softmax over s, context[t,b,h] = sum_s attn[s,t,b]*src[s,b,h]
// float4 h-quads, s-parity split across thread halves + smem reduction.
// Per thread: 32 LDG.128, 32 FMA per load.
// ---------------------------------------------------------------------------
__global__ __launch_bounds__(256) void softmax_context_kernel(
    const float* __restrict__ src,
    float* __restrict__ out)
{
    __shared__ float  w[8][64];
    __shared__ float4 red[8][128];   // 16 KB partial sums

    const int b   = blockIdx.y;
    const int t0  = blockIdx.x * 8;
    const int tid = threadIdx.x;
    const int wi   = tid >> 5;
    const int lane = tid & 31;

    // --- softmax: one warp per t ---
    const float* srow = g_scores + ((t0 + wi) * BATCH + b) * SRC;
    float v0 = srow[lane];
    float v1 = srow[lane + 32];
    float mx = fmaxf(v0, v1);
#pragma unroll
    for (int o = 16; o > 0; o >>= 1)
        mx = fmaxf(mx, __shfl_xor_sync(0xffffffffu, mx, o));
    float e0 = __expf(v0 - mx);
    float e1 = __expf(v1 - mx);
    float sum = e0 + e1;
#pragma unroll
    for (int o = 16; o > 0; o >>= 1)
        sum += __shfl_xor_sync(0xffffffffu, sum, o);
    float inv = 1.0f / sum;
    w[wi][lane]      = e0 * inv;
    w[wi][lane + 32] = e1 * inv;
    __syncthreads();

    // --- context: hq = float4 index, sp = s parity ---
    const int hq = tid & 127;
    const int sp = tid >> 7;

    float4 acc[8];
#pragma unroll
    for (int i = 0; i < 8; i++) acc[i] = make_float4(0.f, 0.f, 0.f, 0.f);

    const float* sb = src + b * HID + hq * 4;
#pragma unroll 4
    for (int s = sp; s < SRC; s += 2) {
        float4 x = *(const float4*)(sb + s * (BATCH * HID));
#pragma unroll
        for (int i = 0; i < 8; i++) {
            float ws = w[i][s];
            acc[i].x = fmaf(ws, x.x, acc[i].x);
            acc[i].y = fmaf(ws, x.y, acc[i].y);
            acc[i].z = fmaf(ws, x.z, acc[i].z);
            acc[i].w = fmaf(ws, x.w, acc[i].w);
        }
    }

    if (sp == 1) {
#pragma unroll
        for (int i = 0; i < 8; i++) red[i][hq] = acc[i];
    }
    __syncthreads();
    if (sp == 0) {
#pragma unroll
        for (int i = 0; i < 8; i++) {
            float4 r = red[i][hq];
            acc[i].x += r.x; acc[i].y += r.y;
            acc[i].z += r.z; acc[i].w += r.w;
            *(float4*)(out + ((t0 + i) * BATCH + b) * HID + hq * 4) = acc[i];
        }
    }
}

// ---------------------------------------------------------------------------
extern "C" void kernel_launch(void* const* d_in, const int* in_sizes, int n_in,
                              void* d_out, int out_size)
{
    const float* h_t  = (const float*)d_in[0];   // (64, 32, 512)
    const float* srce = (const float*)d_in[1];   // (64, 32, 512)
    const float* Wa   = (const float*)d_in[2];   // (1024, 512)
    const float* Va   = (const float*)d_in[3];   // (512,)
    float* out = (float*)d_out;                  // (64, 32, 512)

    (void)in_sizes; (void)n_in; (void)out_size;

    // 0) transpose W halves into g_WT
    transpose_w<<<dim3(16, 16, 2), dim3(32, 8)>>>(Wa);

    // 1) tf32 mma GEMMs: grid (n tiles = 4, m tiles = 32) = 128 CTAs
    const int gemm_smem = 4 * TILEF * (int)sizeof(float);   // 73728 B
    cudaFuncSetAttribute(gemm_mma,
                         cudaFuncAttributeMaxDynamicSharedMemorySize, gemm_smem);
    gemm_mma<<<dim3(4, 32), 256, gemm_smem>>>(h_t, srce);

    // 2) scores: grid (s-halves=2, t-tiles=4, b=32)
    const int smem_bytes = (32 * SSTR + 512) * sizeof(float);
    cudaFuncSetAttribute(scores_kernel,
                         cudaFuncAttributeMaxDynamicSharedMemorySize, smem_bytes);
    scores_kernel<<<dim3(2, 4, 32), 256, smem_bytes>>>(Va);

    // 3) softmax + context
    softmax_context_kernel<<<dim3(8, 32), 256>>>(srce, out);
}

// round 5
// speedup vs baseline: 2.0332x; 1.0348x over previous
#include <cuda_runtime.h>
#include <cuda_bf16.h>
#include <math.h>
#include <cstdint>

// Problem dims
#define TGT   64
#define SRC   64
#define BATCH 32
#define HID   512
#define ATT   512

// Scratch (no cudaMalloc allowed)
__device__ float g_hpart[TGT * BATCH * ATT];   // [t*BATCH+b][a]
__device__ float g_spart[SRC * BATCH * ATT];   // [s*BATCH+b][a]
__device__ float g_scores[TGT * BATCH * SRC];  // [(t*BATCH+b)*SRC + s]
__device__ float g_WT[2 * HID * ATT];          // W transposed (tf32-rounded): [z][n][k]

// ---------------------------------------------------------------------------
// helpers
// ---------------------------------------------------------------------------
__device__ __forceinline__ float to_tf32(float x) {
    uint32_t u;
    asm("cvt.rna.tf32.f32 %0, %1;" : "=r"(u) : "f"(x));
    return __uint_as_float(u);
}

__device__ __forceinline__ float tanh_fast(float x) {
    float y;
    asm("tanh.approx.f32 %0, %1;" : "=f"(y) : "f"(x));
    return y;
}

__device__ __forceinline__ void mma_tf32(float* c, const float* a, const float* b) {
    uint32_t a0 = __float_as_uint(a[0]), a1 = __float_as_uint(a[1]);
    uint32_t a2 = __float_as_uint(a[2]), a3 = __float_as_uint(a[3]);
    uint32_t b0 = __float_as_uint(b[0]), b1 = __float_as_uint(b[1]);
    asm volatile(
        "mma.sync.aligned.m16n8k8.row.col.f32.tf32.tf32.f32 "
        "{%0,%1,%2,%3}, {%4,%5,%6,%7}, {%8,%9}, {%0,%1,%2,%3};"
        : "+f"(c[0]), "+f"(c[1]), "+f"(c[2]), "+f"(c[3])
        : "r"(a0), "r"(a1), "r"(a2), "r"(a3), "r"(b0), "r"(b1));
}

// ---------------------------------------------------------------------------
// Kernel 0: transpose W halves + tf32 rounding: g_WT[z][n][k] = tf32(Wa[z*512+k][n])
// ---------------------------------------------------------------------------
__global__ __launch_bounds__(256) void transpose_w(const float* __restrict__ Wa)
{
    __shared__ float t[32][33];
    const int tx = threadIdx.x, ty = threadIdx.y;
    const int k0 = blockIdx.x * 32, n0 = blockIdx.y * 32, z = blockIdx.z;
#pragma unroll
    for (int r = 0; r < 32; r += 8)
        t[ty + r][tx] = Wa[(z * HID + k0 + ty + r) * ATT + n0 + tx];
    __syncthreads();
#pragma unroll
    for (int r = 0; r < 32; r += 8)
        g_WT[z * HID * ATT + (n0 + ty + r) * HID + k0 + tx] = to_tf32(t[tx][ty + r]);
}

// ---------------------------------------------------------------------------
// Kernel 1: tf32 mma.sync GEMM.  C[m][n] = sum_k A[m][k] * WT[n][k]
// 128x128 CTA tile, KT=32 double-buffered, ONE sync per stage.
// ---------------------------------------------------------------------------
#define KT    32
#define RSTR  36
#define TILEF (128 * RSTR)

__global__ __launch_bounds__(256) void gemm_mma(
    const float* __restrict__ h_t,
    const float* __restrict__ src)
{
    extern __shared__ __align__(16) float sm[];
    float* const Abuf[2] = { sm,         sm + 2 * TILEF };
    float* const Bbuf[2] = { sm + TILEF, sm + 3 * TILEF };

    const int tid  = threadIdx.x;
    const int lane = tid & 31;
    const int wid  = tid >> 5;
    const int g    = lane >> 2;
    const int tg   = lane & 3;

    const int wm = (wid >> 1) * 32;
    const int wn = (wid & 1) * 64;

    const int ntile = blockIdx.x;
    const int mtile = blockIdx.y;
    const int z  = mtile >> 4;
    const float* A = (z == 0) ? h_t : src;
    const float* B = g_WT + z * HID * ATT;
    float*       C = (z == 0) ? g_hpart : g_spart;
    const int m0 = (mtile & 15) * 128;
    const int n0 = ntile * 128;

    float acc[2][8][4];
#pragma unroll
    for (int mi = 0; mi < 2; mi++)
#pragma unroll
        for (int ni = 0; ni < 8; ni++)
#pragma unroll
            for (int j = 0; j < 4; j++) acc[mi][ni][j] = 0.f;

    // ---- stage 0 ----
#pragma unroll
    for (int r = 0; r < 4; r++) {
        const int idx = r * 256 + tid;
        const int row = idx >> 3;
        const int c4  = idx & 7;
        float4 av = *(const float4*)(A + (m0 + row) * HID + c4 * 4);
        float4 bv = *(const float4*)(B + (n0 + row) * HID + c4 * 4);
        float* da = Abuf[0] + row * RSTR + c4 * 4;
        float* db = Bbuf[0] + row * RSTR + c4 * 4;
        *(float4*)da = make_float4(to_tf32(av.x), to_tf32(av.y), to_tf32(av.z), to_tf32(av.w));
        *(float4*)db = bv;   // already tf32-rounded
    }
    __syncthreads();

    for (int s = 0; s < 16; s++) {
        const int cur = s & 1;
        float4 ra[4], rb[4];
        if (s < 15) {
            const int kt = (s + 1) * KT;
#pragma unroll
            for (int r = 0; r < 4; r++) {
                const int idx = r * 256 + tid;
                const int row = idx >> 3;
                const int c4  = idx & 7;
                ra[r] = *(const float4*)(A + (m0 + row) * HID + kt + c4 * 4);
                rb[r] = *(const float4*)(B + (n0 + row) * HID + kt + c4 * 4);
            }
        }

        // ---- compute current buffer: 4 k-steps of 8 ----
        const float* Ab = Abuf[cur];
        const float* Bb = Bbuf[cur];
#pragma unroll
        for (int ks = 0; ks < 4; ks++) {
            const int k0 = ks * 8;
            float a[2][4];
#pragma unroll
            for (int mi = 0; mi < 2; mi++) {
                const float* ap = Ab + (wm + mi * 16 + g) * RSTR + k0 + tg;
                a[mi][0] = ap[0];
                a[mi][1] = ap[8 * RSTR];
                a[mi][2] = ap[4];
                a[mi][3] = ap[8 * RSTR + 4];
            }
            float b[8][2];
#pragma unroll
            for (int ni = 0; ni < 8; ni++) {
                const float* bp = Bb + (wn + ni * 8 + g) * RSTR + k0 + tg;
                b[ni][0] = bp[0];
                b[ni][1] = bp[4];
            }
#pragma unroll
            for (int mi = 0; mi < 2; mi++)
#pragma unroll
                for (int ni = 0; ni < 8; ni++)
                    mma_tf32(acc[mi][ni], a[mi], b[ni]);
        }

        // ---- STS next buffer (safe: it was last read before the previous sync)
        if (s < 15) {
            const int nxt = cur ^ 1;
#pragma unroll
            for (int r = 0; r < 4; r++) {
                const int idx = r * 256 + tid;
                const int row = idx >> 3;
                const int c4  = idx & 7;
                float* da = Abuf[nxt] + row * RSTR + c4 * 4;
                float* db = Bbuf[nxt] + row * RSTR + c4 * 4;
                *(float4*)da = make_float4(to_tf32(ra[r].x), to_tf32(ra[r].y),
                                           to_tf32(ra[r].z), to_tf32(ra[r].w));
                *(float4*)db = rb[r];
            }
            __syncthreads();
        }
    }

    // ---- writeback ----
#pragma unroll
    for (int mi = 0; mi < 2; mi++) {
#pragma unroll
        for (int ni = 0; ni < 8; ni++) {
            const int row = m0 + wm + mi * 16 + g;
            const int col = n0 + wn + ni * 8 + 2 * tg;
            *(float2*)(C + row * ATT + col)       = make_float2(acc[mi][ni][0], acc[mi][ni][1]);
            *(float2*)(C + (row + 8) * ATT + col) = make_float2(acc[mi][ni][2], acc[mi][ni][3]);
        }
    }
}

// ---------------------------------------------------------------------------
// Kernel 2: scores[s,t,b] = sum_a tanh(h_part[t,b,a] + s_part[s,b,a]) * Va[a]
// (unchanged — at MUFU.TANH floor)
// ---------------------------------------------------------------------------
#define SSTR 516

__global__ __launch_bounds__(256) void scores_kernel(
    const float* __restrict__ Va)
{
    extern __shared__ float smem[];
    float* hs = smem;                 // 16 * SSTR
    float* ss = smem + 16 * SSTR;     // 16 * SSTR
    float* va = smem + 32 * SSTR;     // 512

    const int b     = blockIdx.z;
    const int t0    = blockIdx.y * 16;
    const int sbase = blockIdx.x * 32;
    const int tid   = threadIdx.x;

    va[tid]       = Va[tid];
    va[tid + 256] = Va[tid + 256];

#pragma unroll
    for (int r = 0; r < 8; r++) {
        int idx  = r * 256 + tid;
        int row  = idx >> 7;
        int col4 = idx & 127;
        float4 v = *(const float4*)(g_hpart + ((t0 + row) * BATCH + b) * ATT + col4 * 4);
        *(float4*)(hs + row * SSTR + col4 * 4) = v;
    }

    const int si = tid & 15;
    const int ti = tid >> 4;

    for (int sc = 0; sc < 32; sc += 16) {
        __syncthreads();
#pragma unroll
        for (int r = 0; r < 8; r++) {
            int idx  = r * 256 + tid;
            int row  = idx >> 7;
            int col4 = idx & 127;
            float4 v = *(const float4*)(g_spart + ((sbase + sc + row) * BATCH + b) * ATT + col4 * 4);
            *(float4*)(ss + row * SSTR + col4 * 4) = v;
        }
        __syncthreads();

        const float* hp = hs + ti * SSTR;
        const float* sp = ss + si * SSTR;
        float acc = 0.f;
#pragma unroll 4
        for (int a = 0; a < 512; a += 4) {
            float4 h4 = *(const float4*)(hp + a);
            float4 s4 = *(const float4*)(sp + a);
            float4 v4 = *(const float4*)(va + a);
            acc = fmaf(tanh_fast(h4.x + s4.x), v4.x, acc);
            acc = fmaf(tanh_fast(h4.y + s4.y), v4.y, acc);
            acc = fmaf(tanh_fast(h4.z + s4.z), v4.z, acc);
            acc = fmaf(tanh_fast(h4.w + s4.w), v4.w, acc);
        }
        const int s = sbase + sc + si;
        const int t = t0 + ti;
        g_scores[(t * BATCH + b) * SRC + s] = acc;
    }
}

// ---------------------------------------------------------------------------
// Kernel 3: softmax over s, context[t,b,h] = sum_s attn[s,t,b]*src[s,b,h]
// 512 threads: hq = tid&127 (float4 of h), sq = tid>>7 (4-way s split),
// smem partial reduction. 2 blocks/SM -> 32 warps/SM.
// ---------------------------------------------------------------------------
__global__ __launch_bounds__(512) void softmax_context_kernel(
    const float* __restrict__ src,
    float* __restrict__ out)
{
    extern __shared__ float dsm[];
    float (*w)[64] = (float(*)[64])dsm;            // 8*64 floats = 2KB
    float4* red = (float4*)(dsm + 512);            // 3*8*128 float4 = 48KB

    const int b   = blockIdx.y;
    const int t0  = blockIdx.x * 8;
    const int tid = threadIdx.x;
    const int wi   = tid >> 5;
    const int lane = tid & 31;

    // --- softmax: warps 0-7, one t each ---
    if (wi < 8) {
        const float* srow = g_scores + ((t0 + wi) * BATCH + b) * SRC;
        float v0 = srow[lane];
        float v1 = srow[lane + 32];
        float mx = fmaxf(v0, v1);
#pragma unroll
        for (int o = 16; o > 0; o >>= 1)
            mx = fmaxf(mx, __shfl_xor_sync(0xffffffffu, mx, o));
        float e0 = __expf(v0 - mx);
        float e1 = __expf(v1 - mx);
        float sum = e0 + e1;
#pragma unroll
        for (int o = 16; o > 0; o >>= 1)
            sum += __shfl_xor_sync(0xffffffffu, sum, o);
        float inv = 1.0f / sum;
        w[wi][lane]      = e0 * inv;
        w[wi][lane + 32] = e1 * inv;
    }
    __syncthreads();

    // --- context ---
    const int hq = tid & 127;
    const int sq = tid >> 7;      // 0..3
    const int s0 = sq * 16;

    float4 acc[8];
#pragma unroll
    for (int i = 0; i < 8; i++) acc[i] = make_float4(0.f, 0.f, 0.f, 0.f);

    const float* sb = src + b * HID + hq * 4;
#pragma unroll 4
    for (int i = 0; i < 16; i++) {
        const int s = s0 + i;
        float4 x = *(const float4*)(sb + s * (BATCH * HID));
#pragma unroll
        for (int j = 0; j < 8; j++) {
            float ws = w[j][s];
            acc[j].x = fmaf(ws, x.x, acc[j].x);
            acc[j].y = fmaf(ws, x.y, acc[j].y);
            acc[j].z = fmaf(ws, x.z, acc[j].z);
            acc[j].w = fmaf(ws, x.w, acc[j].w);
        }
    }

    if (sq > 0) {
#pragma unroll
        for (int j = 0; j < 8; j++)
            red[((sq - 1) * 8 + j) * 128 + hq] = acc[j];
    }
    __syncthreads();
    if (sq == 0) {
#pragma unroll
        for (int j = 0; j < 8; j++) {
            float4 r0 = red[(0 * 8 + j) * 128 + hq];
            float4 r1 = red[(1 * 8 + j) * 128 + hq];
            float4 r2 = red[(2 * 8 + j) * 128 + hq];
            acc[j].x += r0.x + r1.x + r2.x;
            acc[j].y += r0.y + r1.y + r2.y;
            acc[j].z += r0.z + r1.z + r2.z;
            acc[j].w += r0.w + r1.w + r2.w;
            *(float4*)(out + ((t0 + j) * BATCH + b) * HID + hq * 4) = acc[j];
        }
    }
}

// ---------------------------------------------------------------------------
extern "C" void kernel_launch(void* const* d_in, const int* in_sizes, int n_in,
                              void* d_out, int out_size)
{
    const float* h_t  = (const float*)d_in[0];   // (64, 32, 512)
    const float* srce = (const float*)d_in[1];   // (64, 32, 512)
    const float* Wa   = (const float*)d_in[2];   // (1024, 512)
    const float* Va   = (const float*)d_in[3];   // (512,)
    float* out = (float*)d_out;                  // (64, 32, 512)

    (void)in_sizes; (void)n_in; (void)out_size;

    // 0) transpose + tf32-round W halves into g_WT
    transpose_w<<<dim3(16, 16, 2), dim3(32, 8)>>>(Wa);

    // 1) tf32 mma GEMMs: grid (n tiles = 4, m tiles = 32) = 128 CTAs
    const int gemm_smem = 4 * TILEF * (int)sizeof(float);   // 73728 B
    cudaFuncSetAttribute(gemm_mma,
                         cudaFuncAttributeMaxDynamicSharedMemorySize, gemm_smem);
    gemm_mma<<<dim3(4, 32), 256, gemm_smem>>>(h_t, srce);

    // 2) scores: grid (s-halves=2, t-tiles=4, b=32)
    const int smem_bytes = (32 * SSTR + 512) * sizeof(float);
    cudaFuncSetAttribute(scores_kernel,
                         cudaFuncAttributeMaxDynamicSharedMemorySize, smem_bytes);
    scores_kernel<<<dim3(2, 4, 32), 256, smem_bytes>>>(Va);

    // 3) softmax + context: 512 threads, 4-way s-split, 50KB dyn smem
    const int smc_smem = (512 + 3 * 8 * 128 * 4) * (int)sizeof(float);  // 51200 B
    cudaFuncSetAttribute(softmax_context_kernel,
                         cudaFuncAttributeMaxDynamicSharedMemorySize, smc_smem);
    softmax_context_kernel<<<dim3(8, 32), 512, smc_smem>>>(srce, out);
}